// round 1
// baseline (speedup 1.0000x reference)
#include <cuda_runtime.h>

#define THREADS 128
#define RPC 8          // rows per CTA
#define WS 132         // Wt row stride (floats)
#define XS 132         // x / qk row stride (floats)

// shared memory layout (float offsets)
#define OFF_W   0
#define OFF_X   (128*WS)            // 16896
#define OFF_QK  (OFF_X + 32*XS)     // 21120
#define OFF_B   (OFF_QK + 32*XS)    // 25344
#define OFF_WR  (OFF_B + 128)       // 25472
#define OFF_CWS (OFF_WR + 32)       // 25504
#define OFF_CS  (OFF_CWS + 128)     // 25632
#define OFF_IDS (OFF_CS + 32)       // 25664
#define SMEM_FLOATS (OFF_IDS + 32)  // 25696 floats = 102784 bytes

__global__ __launch_bounds__(THREADS, 2)
void concept_emb_kernel(const int*   __restrict__ g_ids,
                        const float* __restrict__ g_mask,
                        const float* __restrict__ g_times,
                        const float* __restrict__ g_emb,
                        const float* __restrict__ g_qW,
                        const float* __restrict__ g_qb,
                        const float* __restrict__ g_kW,
                        const float* __restrict__ g_kb,
                        const float* __restrict__ g_theta,
                        const float* __restrict__ g_mu,
                        float*       __restrict__ g_out,
                        int n_rows)
{
    extern __shared__ float sm[];
    float* Wt   = sm + OFF_W;    // [128 d][132] : Wt[d][j], j<64 = qW row j, j>=64 = kW row j-64
    float* xs   = sm + OFF_X;    // [32 n][132]
    float* qk   = sm + OFF_QK;   // [32 n][132] : cols 0..63 = q, 64..127 = k
    float* bs   = sm + OFF_B;    // [128] combined bias
    float* wrow = sm + OFF_WR;   // [32] sx * mask per concept
    float* cws  = sm + OFF_CWS;  // [4 warps][32]
    float* cs   = sm + OFF_CS;   // [32] attention column weights
    int*   ids  = (int*)(sm + OFF_IDS);

    const int t    = threadIdx.x;
    const int lane = t & 31;
    const int wid  = t >> 5;
    const int tnb  = t >> 4;   // 0..7  -> n block of 4
    const int tjb  = t & 15;   // 0..15 -> j block of 8

    // ---- stage [qW;kW] transposed into smem (once per CTA) ----
    {
        const float4* q4 = (const float4*)g_qW;
        const float4* k4 = (const float4*)g_kW;
        #pragma unroll
        for (int it = 0; it < 32; ++it) {
            int f  = it * 128 + t;       // float4 index in combined 4096
            int fl = f & 2047;
            float4 v = (f < 2048) ? q4[fl] : k4[fl];
            int j  = (fl >> 5) + ((f < 2048) ? 0 : 64);
            int d0 = (fl & 31) * 4;
            Wt[(d0+0)*WS + j] = v.x;
            Wt[(d0+1)*WS + j] = v.y;
            Wt[(d0+2)*WS + j] = v.z;
            Wt[(d0+3)*WS + j] = v.w;
        }
        bs[t] = (t < 64) ? g_qb[t] : g_kb[t - 64];
    }

    const int row0 = blockIdx.x * RPC;
    for (int rr = 0; rr < RPC; ++rr) {
        const int row = row0 + rr;
        const bool active = (row < n_rows);

        // ---- per-row scalars: ids, pooling weights ----
        if (active && t < 32) {
            int id = g_ids[row * 32 + t];
            ids[t] = id;
            float mk = g_mask[row * 32 + t];
            float tm = g_times[row];
            float z  = g_theta[id] - g_mu[id] * tm;
            float sx = 1.0f / (1.0f + __expf(-z));
            wrow[t] = sx * mk;
        }
        __syncthreads();

        // ---- gather x[32][128] (L2-resident table) ----
        if (active) {
            const float4* emb4 = (const float4*)g_emb;
            #pragma unroll
            for (int r8 = 0; r8 < 8; ++r8) {
                int n = wid * 8 + r8;
                float4 v = emb4[(long)ids[n] * 32 + lane];
                *(float4*)&xs[n * XS + lane * 4] = v;
            }
        }
        __syncthreads();

        // ---- phase 2: [q|k] = x @ [qW;kW]^T, 4n x 8j register tile ----
        if (active) {
            float acc[4][8];
            #pragma unroll
            for (int i = 0; i < 4; ++i)
                #pragma unroll
                for (int u = 0; u < 8; ++u) acc[i][u] = 0.f;

            const float* xp = &xs[(tnb * 4) * XS];
            const float* wp = &Wt[tjb * 8];
            #pragma unroll 2
            for (int ds = 0; ds < 32; ++ds) {
                const int d = ds * 4;
                float xv[4][4];
                #pragma unroll
                for (int i = 0; i < 4; ++i) {
                    float4 v = *(const float4*)(xp + i * XS + d);
                    xv[i][0] = v.x; xv[i][1] = v.y; xv[i][2] = v.z; xv[i][3] = v.w;
                }
                #pragma unroll
                for (int e = 0; e < 4; ++e) {
                    float4 wa = *(const float4*)(wp + (d + e) * WS);
                    float4 wb = *(const float4*)(wp + (d + e) * WS + 4);
                    float wv[8] = {wa.x, wa.y, wa.z, wa.w, wb.x, wb.y, wb.z, wb.w};
                    #pragma unroll
                    for (int i = 0; i < 4; ++i)
                        #pragma unroll
                        for (int u = 0; u < 8; ++u)
                            acc[i][u] = fmaf(xv[i][e], wv[u], acc[i][u]);
                }
            }
            #pragma unroll
            for (int i = 0; i < 4; ++i) {
                int n = tnb * 4 + i;
                float4 o0, o1;
                o0.x = acc[i][0] + bs[tjb*8+0];
                o0.y = acc[i][1] + bs[tjb*8+1];
                o0.z = acc[i][2] + bs[tjb*8+2];
                o0.w = acc[i][3] + bs[tjb*8+3];
                o1.x = acc[i][4] + bs[tjb*8+4];
                o1.y = acc[i][5] + bs[tjb*8+5];
                o1.z = acc[i][6] + bs[tjb*8+6];
                o1.w = acc[i][7] + bs[tjb*8+7];
                *(float4*)&qk[n * XS + tjb * 8]     = o0;
                *(float4*)&qk[n * XS + tjb * 8 + 4] = o1;
            }
        }
        __syncthreads();

        // ---- phase 3: scores (column m = lane), softmax via shuffles,
        //      fold pooling weights into column vector c ----
        if (active) {
            float s[8];
            #pragma unroll
            for (int i = 0; i < 8; ++i) s[i] = 0.f;
            const float* kp = &qk[lane * XS + 64];     // k row m = lane
            const float* qp = &qk[(wid * 8) * XS];     // q rows 8w..8w+7 (broadcast)
            #pragma unroll 2
            for (int hs = 0; hs < 16; ++hs) {
                int h = hs * 4;
                float4 kv = *(const float4*)(kp + h);
                #pragma unroll
                for (int i = 0; i < 8; ++i) {
                    float4 qv = *(const float4*)(qp + i * XS + h);
                    s[i] = fmaf(qv.x, kv.x, s[i]);
                    s[i] = fmaf(qv.y, kv.y, s[i]);
                    s[i] = fmaf(qv.z, kv.z, s[i]);
                    s[i] = fmaf(qv.w, kv.w, s[i]);
                }
            }
            float cpart = 0.f;
            #pragma unroll
            for (int i = 0; i < 8; ++i) {
                float v = s[i] * 0.125f;   // / sqrt(H=64)
                float mx = v;
                #pragma unroll
                for (int o = 16; o > 0; o >>= 1)
                    mx = fmaxf(mx, __shfl_xor_sync(0xffffffffu, mx, o));
                float ex = __expf(v - mx);
                float sum = ex;
                #pragma unroll
                for (int o = 16; o > 0; o >>= 1)
                    sum += __shfl_xor_sync(0xffffffffu, sum, o);
                // weight w_n / rowsum folded into exp directly
                cpart = fmaf(__fdividef(wrow[wid * 8 + i], sum), ex, cpart);
            }
            cws[wid * 32 + lane] = cpart;
        }
        __syncthreads();

        if (active && t < 32)
            cs[t] = cws[t] + cws[32 + t] + cws[64 + t] + cws[96 + t];
        __syncthreads();

        // ---- phase 4: pooled[d] = sum_m c[m] * x[m][d] ----
        if (active) {
            float o = 0.f;
            #pragma unroll
            for (int m = 0; m < 32; ++m)
                o = fmaf(cs[m], xs[m * XS + t], o);
            g_out[(long)row * 128 + t] = o;
        }
        // no trailing sync needed: next iteration's writes (ids/wrow) are
        // disjoint from phase-4 reads (xs/cs); xs is only overwritten after
        // the next step-1 __syncthreads().
    }
}

extern "C" void kernel_launch(void* const* d_in, const int* in_sizes, int n_in,
                              void* d_out, int out_size)
{
    (void)n_in; (void)out_size;
    const int*   g_ids   = (const int*)  d_in[0];
    const float* g_mask  = (const float*)d_in[1];
    const float* g_times = (const float*)d_in[2];
    const float* g_emb   = (const float*)d_in[3];
    const float* g_qW    = (const float*)d_in[4];
    const float* g_qb    = (const float*)d_in[5];
    const float* g_kW    = (const float*)d_in[6];
    const float* g_kb    = (const float*)d_in[7];
    const float* g_theta = (const float*)d_in[8];
    const float* g_mu    = (const float*)d_in[9];
    float* g_out = (float*)d_out;

    const int n_rows = in_sizes[2];               // B*LS = 16384
    const int smem_bytes = SMEM_FLOATS * sizeof(float);

    cudaFuncSetAttribute(concept_emb_kernel,
                         cudaFuncAttributeMaxDynamicSharedMemorySize, smem_bytes);

    const int blocks = (n_rows + RPC - 1) / RPC;  // 2048
    concept_emb_kernel<<<blocks, THREADS, smem_bytes>>>(
        g_ids, g_mask, g_times, g_emb, g_qW, g_qb, g_kW, g_kb,
        g_theta, g_mu, g_out, n_rows);
}

// round 3
// speedup vs baseline: 1.2792x; 1.2792x over previous
#include <cuda_runtime.h>

#define THREADS 128
#define RPC 8          // rows per CTA
#define WS 128         // Wt row stride (floats) — no pad needed (loads are BW-floor)
#define XS 132         // x / qk row stride (floats), mult of 4, not mult of 32

// shared memory layout (float offsets)
#define OFF_W   0
#define OFF_X   (128*WS)            // 16384
#define OFF_QK  (OFF_X + 32*XS)     // +4224
#define OFF_B   (OFF_QK + 32*XS)    // +4224
#define OFF_WR  (OFF_B + 128)
#define OFF_CWS (OFF_WR + 32)
#define OFF_CS  (OFF_CWS + 128)
#define SMEM_FLOATS (OFF_CS + 32)   // 25152 floats = 100608 B -> 2 CTAs/SM

// ---- packed fp32x2 helpers (sm_10x FFMA2 path, PTX-only) ----
__device__ __forceinline__ unsigned long long ffma2(unsigned long long a,
                                                    unsigned long long b,
                                                    unsigned long long c) {
    unsigned long long d;
    asm("fma.rn.f32x2 %0, %1, %2, %3;" : "=l"(d) : "l"(a), "l"(b), "l"(c));
    return d;
}
__device__ __forceinline__ unsigned long long dup2(float x) {
    unsigned long long r;
    asm("mov.b64 %0, {%1, %1};" : "=l"(r) : "f"(x));
    return r;
}
__device__ __forceinline__ void unpack2(unsigned long long v, float& lo, float& hi) {
    asm("mov.b64 {%0, %1}, %2;" : "=f"(lo), "=f"(hi) : "l"(v));
}

__global__ __launch_bounds__(THREADS, 2)
void concept_emb_kernel(const int*   __restrict__ g_ids,
                        const float* __restrict__ g_mask,
                        const float* __restrict__ g_times,
                        const float* __restrict__ g_emb,
                        const float* __restrict__ g_qW,
                        const float* __restrict__ g_qb,
                        const float* __restrict__ g_kW,
                        const float* __restrict__ g_kb,
                        const float* __restrict__ g_theta,
                        const float* __restrict__ g_mu,
                        float*       __restrict__ g_out,
                        int n_rows)
{
    extern __shared__ float sm[];
    float* Wt   = sm + OFF_W;    // [128 d][128] : Wt[d][j], j<64 = qW row j, j>=64 = kW row j-64
    float* xs   = sm + OFF_X;    // [32 n][132]
    float* qk   = sm + OFF_QK;   // [32 n][132] : cols 0..63 = q, 64..127 = k
    float* bs   = sm + OFF_B;    // [128] combined bias
    float* wrow = sm + OFF_WR;   // [32] sx * mask per concept
    float* cws  = sm + OFF_CWS;  // [4 warps][32]
    float* cs   = sm + OFF_CS;   // [32] attention column weights

    const int t    = threadIdx.x;
    const int lane = t & 31;
    const int wid  = t >> 5;
    const int tnb  = t >> 4;   // 0..7  -> n block of 4 (x loads broadcast in-warp)
    const int tjb  = t & 15;   // 0..15 -> j tile {4tjb..+3} U {4tjb+64..+67}

    // ---- stage [qW;kW] transposed into smem (once per CTA) ----
    {
        const float4* q4 = (const float4*)g_qW;
        const float4* k4 = (const float4*)g_kW;
        #pragma unroll
        for (int it = 0; it < 32; ++it) {
            int f  = it * 128 + t;       // float4 index in combined 4096
            int fl = f & 2047;
            float4 v = (f < 2048) ? q4[fl] : k4[fl];
            int j  = (fl >> 5) + ((f < 2048) ? 0 : 64);
            int d0 = (fl & 31) * 4;
            Wt[(d0+0)*WS + j] = v.x;
            Wt[(d0+1)*WS + j] = v.y;
            Wt[(d0+2)*WS + j] = v.z;
            Wt[(d0+3)*WS + j] = v.w;
        }
        bs[t] = (t < 64) ? g_qb[t] : g_kb[t - 64];
    }
    __syncthreads();

    // bias for this thread's j-tile, held in registers across all rows
    const float4 bq = *(const float4*)&bs[4 * tjb];
    const float4 bk = *(const float4*)&bs[4 * tjb + 64];

    const int row0 = blockIdx.x * RPC;
    for (int rr = 0; rr < RPC; ++rr) {
        const int row = row0 + rr;
        const bool active = (row < n_rows);

        // ---- gather x[32][128] + per-concept pooling weights (no sync between) ----
        if (active) {
            const float4* emb4 = (const float4*)g_emb;
            #pragma unroll
            for (int r8 = 0; r8 < 8; ++r8) {
                int n = wid * 8 + r8;
                int id = g_ids[row * 32 + n];           // warp-uniform broadcast LDG
                float4 v = emb4[(long)id * 32 + lane];
                *(float4*)&xs[n * XS + lane * 4] = v;
            }
            if (t < 32) {
                int id = g_ids[row * 32 + t];
                float mk = g_mask[row * 32 + t];
                float tm = g_times[row];
                float z  = g_theta[id] - g_mu[id] * tm;
                float sx = 1.0f / (1.0f + __expf(-z));
                wrow[t] = sx * mk;
            }
        }
        __syncthreads();

        // ---- phase 2: [q|k] = x @ [qW;kW]^T, 4n x 8j tile, packed f32x2 ----
        if (active) {
            unsigned long long acc2[4][4];   // [i][jpair]: {4tjb+0,1},{+2,3},{+64,+65},{+66,+67}
            #pragma unroll
            for (int i = 0; i < 4; ++i)
                #pragma unroll
                for (int u = 0; u < 4; ++u) acc2[i][u] = 0ULL;

            const float* xp = &xs[(tnb * 4) * XS];
            const float* wp = &Wt[4 * tjb];
            #pragma unroll 2
            for (int ds = 0; ds < 32; ++ds) {
                const int d = ds * 4;
                float4 xv[4];
                #pragma unroll
                for (int i = 0; i < 4; ++i)
                    xv[i] = *(const float4*)(xp + i * XS + d);
                #pragma unroll
                for (int e = 0; e < 4; ++e) {
                    const float* wr = wp + (d + e) * WS;
                    ulonglong2 wq = *(const ulonglong2*)(wr);
                    ulonglong2 wk = *(const ulonglong2*)(wr + 64);
                    #pragma unroll
                    for (int i = 0; i < 4; ++i) {
                        const float* xf = (const float*)&xv[i];
                        unsigned long long xd = dup2(xf[e]);
                        acc2[i][0] = ffma2(xd, wq.x, acc2[i][0]);
                        acc2[i][1] = ffma2(xd, wq.y, acc2[i][1]);
                        acc2[i][2] = ffma2(xd, wk.x, acc2[i][2]);
                        acc2[i][3] = ffma2(xd, wk.y, acc2[i][3]);
                    }
                }
            }
            #pragma unroll
            for (int i = 0; i < 4; ++i) {
                int n = tnb * 4 + i;
                float q0,q1,q2,q3,k0,k1,k2,k3;
                unpack2(acc2[i][0], q0, q1);
                unpack2(acc2[i][1], q2, q3);
                unpack2(acc2[i][2], k0, k1);
                unpack2(acc2[i][3], k2, k3);
                float4 oq = {q0 + bq.x, q1 + bq.y, q2 + bq.z, q3 + bq.w};
                float4 ok = {k0 + bk.x, k1 + bk.y, k2 + bk.z, k3 + bk.w};
                *(float4*)&qk[n * XS + 4 * tjb]      = oq;
                *(float4*)&qk[n * XS + 4 * tjb + 64] = ok;
            }
        }
        __syncthreads();

        // ---- phase 3: scores (column m = lane), softmax via shuffles,
        //      fold pooling weights into column vector c; packed f32x2 dot ----
        if (active) {
            unsigned long long s2[8];
            #pragma unroll
            for (int i = 0; i < 8; ++i) s2[i] = 0ULL;
            const float* kp = &qk[lane * XS + 64];     // k row m = lane
            const float* qp = &qk[(wid * 8) * XS];     // q rows 8w..8w+7 (broadcast)
            #pragma unroll 2
            for (int hs = 0; hs < 16; ++hs) {
                const int h = hs * 4;
                ulonglong2 kv = *(const ulonglong2*)(kp + h);
                #pragma unroll
                for (int i = 0; i < 8; ++i) {
                    ulonglong2 qv = *(const ulonglong2*)(qp + i * XS + h);
                    s2[i] = ffma2(qv.x, kv.x, s2[i]);
                    s2[i] = ffma2(qv.y, kv.y, s2[i]);
                }
            }
            float cpart = 0.f;
            #pragma unroll
            for (int i = 0; i < 8; ++i) {
                float a, b;
                unpack2(s2[i], a, b);
                float v = (a + b) * 0.125f;            // / sqrt(H=64)
                float mx = v;
                #pragma unroll
                for (int o = 16; o > 0; o >>= 1)
                    mx = fmaxf(mx, __shfl_xor_sync(0xffffffffu, mx, o));
                float ex = __expf(v - mx);
                float sum = ex;
                #pragma unroll
                for (int o = 16; o > 0; o >>= 1)
                    sum += __shfl_xor_sync(0xffffffffu, sum, o);
                cpart = fmaf(__fdividef(wrow[wid * 8 + i], sum), ex, cpart);
            }
            cws[wid * 32 + lane] = cpart;
        }
        __syncthreads();

        if (active && t < 32)
            cs[t] = cws[t] + cws[32 + t] + cws[64 + t] + cws[96 + t];
        __syncthreads();

        // ---- phase 4: pooled[d] = sum_m c[m] * x[m][d] ----
        if (active) {
            float o = 0.f;
            #pragma unroll
            for (int m = 0; m < 32; ++m)
                o = fmaf(cs[m], xs[m * XS + t], o);
            g_out[(long)row * 128 + t] = o;
        }
        // next iteration's first writes (xs/wrow) happen only after its own
        // __syncthreads(); phase-4 reads are protected by the cs sync above.
        __syncthreads();
    }
}

extern "C" void kernel_launch(void* const* d_in, const int* in_sizes, int n_in,
                              void* d_out, int out_size)
{
    (void)n_in; (void)out_size;
    const int*   g_ids   = (const int*)  d_in[0];
    const float* g_mask  = (const float*)d_in[1];
    const float* g_times = (const float*)d_in[2];
    const float* g_emb   = (const float*)d_in[3];
    const float* g_qW    = (const float*)d_in[4];
    const float* g_qb    = (const float*)d_in[5];
    const float* g_kW    = (const float*)d_in[6];
    const float* g_kb    = (const float*)d_in[7];
    const float* g_theta = (const float*)d_in[8];
    const float* g_mu    = (const float*)d_in[9];
    float* g_out = (float*)d_out;

    const int n_rows = in_sizes[2];               // B*LS = 16384
    const int smem_bytes = SMEM_FLOATS * sizeof(float);

    cudaFuncSetAttribute(concept_emb_kernel,
                         cudaFuncAttributeMaxDynamicSharedMemorySize, smem_bytes);

    const int blocks = (n_rows + RPC - 1) / RPC;  // 2048
    concept_emb_kernel<<<blocks, THREADS, smem_bytes>>>(
        g_ids, g_mask, g_times, g_emb, g_qW, g_qb, g_kW, g_kb,
        g_theta, g_mu, g_out, n_rows);
}